// round 2
// baseline (speedup 1.0000x reference)
#include <cuda_runtime.h>
#include <math.h>

// Problem constants (GptOssExperts: B=1, S=1024, H=D=2880, E=8)
#define TOK   1024
#define HDIM  2880
#define DDIM  2880
#define NEXP  8
#define GU    (2*DDIM)      // 5760 gate_up columns
#define ALPHA 1.702f
#define LIMIT 7.0f

// Activation scratch: act[e][t][d] = (up+1)*glu, 8*1024*2880 floats = 94.4 MB
__device__ float g_act[(size_t)NEXP * TOK * DDIM];

// ---------------------------------------------------------------------------
// Kernel A: for each expert e, gate_up GEMM + bias + SwiGLU epilogue -> g_act
//   gate_up[e,t,c] = sum_h x[t,h] * Wgu[e,h,c] + bgu[e,c]
//   gate = col 2d, up = col 2d+1
// Tile: 128 tokens x 64 d-pairs (=128 gu columns). 256 threads, KT=16.
// ---------------------------------------------------------------------------
__global__ __launch_bounds__(256, 2)
void gate_up_kernel(const float* __restrict__ x,
                    const float* __restrict__ Wgu,
                    const float* __restrict__ bgu)
{
    const int e  = blockIdx.z;
    const int m0 = blockIdx.y * 128;   // token base
    const int d0 = blockIdx.x * 64;    // d-pair base
    const int c0 = d0 * 2;             // gu column base

    __shared__ float As[16][128];      // As[k][m] = x[m0+m][k0+k]
    __shared__ float Bs[16][128];      // Bs[k][j] = Wgu[e][k0+k][c0+j]

    const int tid = threadIdx.x;
    const int tx  = tid & 15;          // 0..15 column group
    const int ty  = tid >> 4;          // 0..15 row group

    // A-tile loader mapping: m = tid%128, k quads {lk..lk+3, lk+8..lk+11}
    const int lm = tid & 127;
    const int lk = (tid >> 7) * 4;     // 0 or 4
    const float* xA = x + (size_t)(m0 + lm) * HDIM;

    // B-tile loader mapping: k = tid/16, j quads {bj, bj+64}
    const int bk = tid >> 4;
    const int bj = (tid & 15) * 4;
    const float* WB = Wgu + (size_t)e * HDIM * GU + c0;

    float4 pa0, pa1, pb0, pb1;
    {
        pa0 = *(const float4*)(xA + lk);
        pa1 = *(const float4*)(xA + lk + 8);
        const float* wr = WB + (size_t)bk * GU;
        pb0 = *(const float4*)(wr + bj);
        pb1 = *(const float4*)(wr + bj + 64);
    }

    float ag[8][4], au[8][4];
    #pragma unroll
    for (int i = 0; i < 8; ++i)
        #pragma unroll
        for (int j = 0; j < 4; ++j) { ag[i][j] = 0.f; au[i][j] = 0.f; }

    const int NT = HDIM / 16;          // 180
    for (int kt = 0; kt < NT; ++kt) {
        // commit prefetched tile to SMEM
        As[lk + 0][lm] = pa0.x;  As[lk + 1][lm] = pa0.y;
        As[lk + 2][lm] = pa0.z;  As[lk + 3][lm] = pa0.w;
        As[lk + 8][lm] = pa1.x;  As[lk + 9][lm] = pa1.y;
        As[lk +10][lm] = pa1.z;  As[lk +11][lm] = pa1.w;
        *(float4*)&Bs[bk][bj]      = pb0;
        *(float4*)&Bs[bk][bj + 64] = pb1;
        __syncthreads();

        if (kt + 1 < NT) {
            const int k0n = (kt + 1) * 16;
            pa0 = *(const float4*)(xA + k0n + lk);
            pa1 = *(const float4*)(xA + k0n + lk + 8);
            const float* wr = WB + (size_t)(k0n + bk) * GU;
            pb0 = *(const float4*)(wr + bj);
            pb1 = *(const float4*)(wr + bj + 64);
        }

        #pragma unroll
        for (int k = 0; k < 16; ++k) {
            float4 a0 = *(const float4*)&As[k][ty * 4];
            float4 a1 = *(const float4*)&As[k][ty * 4 + 64];
            float4 b0 = *(const float4*)&Bs[k][tx * 8];
            float4 b1 = *(const float4*)&Bs[k][tx * 8 + 4];
            float am[8] = {a0.x, a0.y, a0.z, a0.w, a1.x, a1.y, a1.z, a1.w};
            float gw[4] = {b0.x, b0.z, b1.x, b1.z};
            float uw[4] = {b0.y, b0.w, b1.y, b1.w};
            #pragma unroll
            for (int mi = 0; mi < 8; ++mi)
                #pragma unroll
                for (int di = 0; di < 4; ++di) {
                    ag[mi][di] = fmaf(am[mi], gw[di], ag[mi][di]);
                    au[mi][di] = fmaf(am[mi], uw[di], au[mi][di]);
                }
        }
        __syncthreads();
    }

    // Epilogue: bias + clamp + SwiGLU, store activation
    const float* bptr = bgu + (size_t)e * GU + c0;
    #pragma unroll
    for (int mi = 0; mi < 8; ++mi) {
        const int mloc = (mi < 4) ? (ty * 4 + mi) : (64 + ty * 4 + mi - 4);
        const int m    = m0 + mloc;
        float* ap = g_act + ((size_t)e * TOK + m) * DDIM + d0 + tx * 4;
        #pragma unroll
        for (int di = 0; di < 4; ++di) {
            const int j = tx * 8 + di * 2;
            float gate = ag[mi][di] + bptr[j];
            float up   = au[mi][di] + bptr[j + 1];
            gate = fminf(gate, LIMIT);
            up   = fminf(fmaxf(up, -LIMIT), LIMIT);
            // gate * sigmoid(ALPHA*gate) = gate / (1 + exp(-ALPHA*gate))
            float glu = gate / (1.0f + expf(-ALPHA * gate));
            ap[di] = (up + 1.0f) * glu;
        }
    }
}

// ---------------------------------------------------------------------------
// Kernel B: out[t,h] = sum_e rw[t,e] * ( sum_d act[e,t,d]*Wd[e,d,h] + bd[e,h] )
// rw folded into A-tile at load time; expert loop inside CTA (no atomics).
// Tile: 128 tokens x 64 h. 256 threads, KT=16.
// ---------------------------------------------------------------------------
__global__ __launch_bounds__(256, 2)
void down_kernel(const float* __restrict__ rw,
                 const float* __restrict__ Wd,
                 const float* __restrict__ bd,
                 float* __restrict__ out)
{
    const int m0 = blockIdx.y * 128;
    const int h0 = blockIdx.x * 64;

    __shared__ float As[16][128];      // As[k][m] = act[e][m0+m][k0+k] * rw[m,e]
    __shared__ float Bs[16][64];       // Bs[k][j] = Wd[e][k0+k][h0+j]

    const int tid = threadIdx.x;
    const int tx  = tid & 15;
    const int ty  = tid >> 4;

    const int lm = tid & 127;
    const int lk = (tid >> 7) * 4;

    const int bk = tid >> 4;
    const int bj = (tid & 15) * 4;

    float acc[8][4];
    #pragma unroll
    for (int i = 0; i < 8; ++i)
        #pragma unroll
        for (int j = 0; j < 4; ++j) acc[i][j] = 0.f;

    const int NT = DDIM / 16;          // 180

    for (int e = 0; e < NEXP; ++e) {
        const float* aA  = g_act + ((size_t)e * TOK + m0 + lm) * DDIM;
        const float  rws = rw[(size_t)(m0 + lm) * NEXP + e];
        const float* WB  = Wd + (size_t)e * DDIM * HDIM + h0;

        float4 pa0, pa1, pb0;
        pa0 = *(const float4*)(aA + lk);
        pa1 = *(const float4*)(aA + lk + 8);
        pb0 = *(const float4*)(WB + (size_t)bk * HDIM + bj);

        for (int kt = 0; kt < NT; ++kt) {
            As[lk + 0][lm] = pa0.x * rws;  As[lk + 1][lm] = pa0.y * rws;
            As[lk + 2][lm] = pa0.z * rws;  As[lk + 3][lm] = pa0.w * rws;
            As[lk + 8][lm] = pa1.x * rws;  As[lk + 9][lm] = pa1.y * rws;
            As[lk +10][lm] = pa1.z * rws;  As[lk +11][lm] = pa1.w * rws;
            *(float4*)&Bs[bk][bj] = pb0;
            __syncthreads();

            if (kt + 1 < NT) {
                const int k0n = (kt + 1) * 16;
                pa0 = *(const float4*)(aA + k0n + lk);
                pa1 = *(const float4*)(aA + k0n + lk + 8);
                pb0 = *(const float4*)(WB + (size_t)(k0n + bk) * HDIM + bj);
            }

            #pragma unroll
            for (int k = 0; k < 16; ++k) {
                float4 a0 = *(const float4*)&As[k][ty * 4];
                float4 a1 = *(const float4*)&As[k][ty * 4 + 64];
                float4 b0 = *(const float4*)&Bs[k][tx * 4];
                float am[8] = {a0.x, a0.y, a0.z, a0.w, a1.x, a1.y, a1.z, a1.w};
                float bm[4] = {b0.x, b0.y, b0.z, b0.w};
                #pragma unroll
                for (int mi = 0; mi < 8; ++mi)
                    #pragma unroll
                    for (int ji = 0; ji < 4; ++ji)
                        acc[mi][ji] = fmaf(am[mi], bm[ji], acc[mi][ji]);
            }
            __syncthreads();
        }
    }

    // Epilogue: add routing-weighted down bias, write output
    #pragma unroll
    for (int mi = 0; mi < 8; ++mi) {
        const int mloc = (mi < 4) ? (ty * 4 + mi) : (64 + ty * 4 + mi - 4);
        const int m    = m0 + mloc;
        #pragma unroll
        for (int ji = 0; ji < 4; ++ji) {
            const int h = h0 + tx * 4 + ji;
            float v = acc[mi][ji];
            #pragma unroll
            for (int e = 0; e < NEXP; ++e)
                v = fmaf(rw[(size_t)m * NEXP + e], bd[(size_t)e * HDIM + h], v);
            out[(size_t)m * HDIM + h] = v;
        }
    }
}

// ---------------------------------------------------------------------------
// Launch
// Inputs (metadata order):
//   0: hidden_states   float32 [1,1024,2880]
//   1: routing_weights float32 [1024,8]
//   2: gate_up_proj    float32 [8,2880,5760]
//   3: gate_up_bias    float32 [8,5760]
//   4: down_proj       float32 [8,2880,2880]
//   5: down_bias       float32 [8,2880]
// Output: float32 [1,1024,2880]
// ---------------------------------------------------------------------------
extern "C" void kernel_launch(void* const* d_in, const int* in_sizes, int n_in,
                              void* d_out, int out_size)
{
    const float* x   = (const float*)d_in[0];
    const float* rw  = (const float*)d_in[1];
    const float* Wgu = (const float*)d_in[2];
    const float* bgu = (const float*)d_in[3];
    const float* Wd  = (const float*)d_in[4];
    const float* bd  = (const float*)d_in[5];
    float* out = (float*)d_out;

    dim3 gridA(GU / 128, TOK / 128, NEXP);   // (45, 8, 8)
    gate_up_kernel<<<gridA, 256>>>(x, Wgu, bgu);

    dim3 gridB(HDIM / 64, TOK / 128);        // (45, 8)
    down_kernel<<<gridB, 256>>>(rw, Wd, bd, out);
}

// round 4
// speedup vs baseline: 2.3944x; 2.3944x over previous
#include <cuda_runtime.h>
#include <cuda_bf16.h>
#include <math.h>

#define TOK 1024
#define HDIM 2880
#define DDIM 2880
#define NEXP 8
#define GUCOLS 5760
#define ALPHA 1.702f
#define LIMIT 7.0f

__device__ __align__(16) __nv_bfloat16 g_wgu_hi[(size_t)NEXP*HDIM*GUCOLS];
__device__ __align__(16) __nv_bfloat16 g_wgu_lo[(size_t)NEXP*HDIM*GUCOLS];
__device__ __align__(16) __nv_bfloat16 g_wd_hi[(size_t)NEXP*DDIM*HDIM];
__device__ __align__(16) __nv_bfloat16 g_wd_lo[(size_t)NEXP*DDIM*HDIM];
__device__ __align__(16) __nv_bfloat16 g_x_hi[(size_t)TOK*HDIM];
__device__ __align__(16) __nv_bfloat16 g_x_lo[(size_t)TOK*HDIM];
__device__ __align__(16) __nv_bfloat16 g_a_hi[(size_t)NEXP*TOK*DDIM];
__device__ __align__(16) __nv_bfloat16 g_a_lo[(size_t)NEXP*TOK*DDIM];

__device__ __forceinline__ unsigned su32(const void* p){
    unsigned a; asm("{ .reg .u64 t; cvta.to.shared.u64 t, %1; cvt.u32.u64 %0, t; }":"=r"(a):"l"(p)); return a;
}
template<int N> __device__ __forceinline__ void cpwait(){
    asm volatile("cp.async.wait_group %0;"::"n"(N):"memory");
}
__device__ __forceinline__ void cpcommit(){
    asm volatile("cp.async.commit_group;":::"memory");
}
__device__ __forceinline__ void cpa16(unsigned d, const void* s){
    asm volatile("cp.async.cg.shared.global [%0], [%1], 16;"::"r"(d),"l"(s):"memory");
}
__device__ __forceinline__ void ldsm4(unsigned* r, unsigned a){
    asm volatile("ldmatrix.sync.aligned.m8n8.x4.shared.b16 {%0,%1,%2,%3}, [%4];"
        :"=r"(r[0]),"=r"(r[1]),"=r"(r[2]),"=r"(r[3]):"r"(a));
}
__device__ __forceinline__ void ldsm2t(unsigned* r, unsigned a){
    asm volatile("ldmatrix.sync.aligned.m8n8.x2.trans.shared.b16 {%0,%1}, [%2];"
        :"=r"(r[0]),"=r"(r[1]):"r"(a));
}
__device__ __forceinline__ void mma_bf(float* c, const unsigned* a, const unsigned* b){
    asm volatile("mma.sync.aligned.m16n8k16.row.col.f32.bf16.bf16.f32 "
        "{%0,%1,%2,%3},{%4,%5,%6,%7},{%8,%9},{%0,%1,%2,%3};"
        : "+f"(c[0]),"+f"(c[1]),"+f"(c[2]),"+f"(c[3])
        : "r"(a[0]),"r"(a[1]),"r"(a[2]),"r"(a[3]),"r"(b[0]),"r"(b[1]));
}

// -------- fp32 -> bf16 hi/lo split --------
__global__ void split_kernel(const float4* __restrict__ src, int which, long long n4){
    __nv_bfloat16 *hi, *lo;
    if(which==0){hi=g_x_hi;lo=g_x_lo;} else if(which==1){hi=g_wgu_hi;lo=g_wgu_lo;} else {hi=g_wd_hi;lo=g_wd_lo;}
    uint2* hp=(uint2*)hi; uint2* lp=(uint2*)lo;
    long long i=(long long)blockIdx.x*blockDim.x+threadIdx.x, st=(long long)gridDim.x*blockDim.x;
    for(; i<n4; i+=st){
        float4 f=src[i];
        __nv_bfloat16 h0=__float2bfloat16_rn(f.x), h1=__float2bfloat16_rn(f.y);
        __nv_bfloat16 h2=__float2bfloat16_rn(f.z), h3=__float2bfloat16_rn(f.w);
        __nv_bfloat16 l0=__float2bfloat16_rn(f.x-__bfloat162float(h0));
        __nv_bfloat16 l1=__float2bfloat16_rn(f.y-__bfloat162float(h1));
        __nv_bfloat16 l2=__float2bfloat16_rn(f.z-__bfloat162float(h2));
        __nv_bfloat16 l3=__float2bfloat16_rn(f.w-__bfloat162float(h3));
        uint2 hv, lv;
        hv.x=(unsigned)__bfloat16_as_ushort(h0)|((unsigned)__bfloat16_as_ushort(h1)<<16);
        hv.y=(unsigned)__bfloat16_as_ushort(h2)|((unsigned)__bfloat16_as_ushort(h3)<<16);
        lv.x=(unsigned)__bfloat16_as_ushort(l0)|((unsigned)__bfloat16_as_ushort(l1)<<16);
        lv.y=(unsigned)__bfloat16_as_ushort(l2)|((unsigned)__bfloat16_as_ushort(l3)<<16);
        hp[i]=hv; lp[i]=lv;
    }
}

// ======================= GEMM1: gate_up + SwiGLU =======================
// CTA tile: 128 tokens x 128 gu-cols (=64 d). 256 thr, warps 2m x 4n (64x32).
// Stage: Ahi[128x32 bf16, stride 80B] Alo | Bhi[32k x 128n, stride 272B] Blo.
#define S1_ALO 10240
#define S1_B   20480
#define S1_BLO 8704
#define S1_STAGE 37888

__global__ __launch_bounds__(256,1)
void gemm1_kernel(const float* __restrict__ rw, const float* __restrict__ bgu)
{
    extern __shared__ __align__(16) char dsm[];
    __shared__ float sBias[128];
    __shared__ float sRw[128];
    const int tid=threadIdx.x, lane=tid&31, w=tid>>5;
    const int e=blockIdx.z, m0=blockIdx.y*128, c0=blockIdx.x*128, dbase=blockIdx.x*64;
    const unsigned db=su32(dsm);
    if(tid<128){
        sBias[tid]=bgu[(size_t)e*GUCOLS+c0+tid];
        sRw[tid]=rw[(size_t)(m0+tid)*NEXP+e];
    }

    const __nv_bfloat16* xh = g_x_hi + (size_t)m0*HDIM;
    const __nv_bfloat16* xl = g_x_lo + (size_t)m0*HDIM;
    const __nv_bfloat16* wh = g_wgu_hi + (size_t)e*HDIM*GUCOLS + c0;
    const __nv_bfloat16* wl = g_wgu_lo + (size_t)e*HDIM*GUCOLS + c0;

    const int ar=tid>>2, ac=tid&3;       // A: rows ar, ar+64; 16B chunk ac
    const int br=tid>>4, bc=tid&15;      // B: k-rows br, br+16; 16B chunk bc

    auto LOAD=[&](int kc,int s){
        const unsigned st=db+(unsigned)s*S1_STAGE;
        const int k0=kc*32;
        cpa16(st+ar*80+ac*16,            xh+(size_t)ar*HDIM+k0+ac*8);
        cpa16(st+(ar+64)*80+ac*16,       xh+(size_t)(ar+64)*HDIM+k0+ac*8);
        cpa16(st+S1_ALO+ar*80+ac*16,     xl+(size_t)ar*HDIM+k0+ac*8);
        cpa16(st+S1_ALO+(ar+64)*80+ac*16,xl+(size_t)(ar+64)*HDIM+k0+ac*8);
        cpa16(st+S1_B+br*272+bc*16,            wh+(size_t)(k0+br)*GUCOLS+bc*8);
        cpa16(st+S1_B+(br+16)*272+bc*16,       wh+(size_t)(k0+br+16)*GUCOLS+bc*8);
        cpa16(st+S1_B+S1_BLO+br*272+bc*16,     wl+(size_t)(k0+br)*GUCOLS+bc*8);
        cpa16(st+S1_B+S1_BLO+(br+16)*272+bc*16,wl+(size_t)(k0+br+16)*GUCOLS+bc*8);
        cpcommit();
    };

    const int mw=(w&1)*64, nw=(w>>1)*32;
    float C[4][4][4];
    #pragma unroll
    for(int i=0;i<4;i++)
        #pragma unroll
        for(int j=0;j<4;j++)
            #pragma unroll
            for(int q=0;q<4;q++) C[i][j][q]=0.f;

    LOAD(0,0); LOAD(1,1);
    const int NCH=HDIM/32; // 90
    for(int kc=0;kc<NCH;kc++){
        if(kc==NCH-1) cpwait<0>(); else cpwait<1>();
        __syncthreads();
        if(kc+2<NCH) LOAD(kc+2,(kc+2)%3);
        const unsigned ab=db+(unsigned)(kc%3)*S1_STAGE;
        const unsigned bb=ab+S1_B;
        #pragma unroll
        for(int ks=0;ks<2;ks++){
            unsigned a_h[4][4],a_l[4][4],b_h[4][2],b_l[4][2];
            const unsigned abase=ab+(mw+(lane&15))*80+((lane>>4)*16)+ks*32;
            #pragma unroll
            for(int mt=0;mt<4;mt++){
                ldsm4(a_h[mt],abase+mt*16*80);
                ldsm4(a_l[mt],abase+S1_ALO+mt*16*80);
            }
            const unsigned bbase=bb+(ks*16+(lane&15))*272;
            #pragma unroll
            for(int nt=0;nt<4;nt++){
                unsigned o=bbase+(nw+nt*8)*2;
                ldsm2t(b_h[nt],o);
                ldsm2t(b_l[nt],o+S1_BLO);
            }
            #pragma unroll
            for(int mt=0;mt<4;mt++)
                #pragma unroll
                for(int nt=0;nt<4;nt++){
                    mma_bf(C[mt][nt],a_h[mt],b_h[nt]);
                    mma_bf(C[mt][nt],a_h[mt],b_l[nt]);
                    mma_bf(C[mt][nt],a_l[mt],b_h[nt]);
                }
        }
    }
    __syncthreads();

    // epilogue: bias + SwiGLU + rw -> sv (fp32), then split to act hi/lo
    float* sv=(float*)dsm;
    const int grp=lane>>2, tq=lane&3;
    #pragma unroll
    for(int mt=0;mt<4;mt++)
        #pragma unroll
        for(int nt=0;nt<4;nt++){
            const int colL=nw+nt*8+tq*2;
            const int d=(nw>>1)+nt*4+tq;
            #pragma unroll
            for(int h=0;h<2;h++){
                const int row=mw+mt*16+grp+h*8;
                float g=C[mt][nt][2*h]  +sBias[colL];
                float u=C[mt][nt][2*h+1]+sBias[colL+1];
                g=fminf(g,LIMIT);
                u=fminf(fmaxf(u,-LIMIT),LIMIT);
                float glu=g/(1.0f+__expf(-ALPHA*g));
                sv[row*68+d]=(u+1.0f)*glu*sRw[row];
            }
        }
    __syncthreads();
    {
        const int row=tid>>1, d0=(tid&1)*32;
        __nv_bfloat16* oh=g_a_hi+((size_t)e*TOK+m0+row)*DDIM+dbase+d0;
        __nv_bfloat16* ol=g_a_lo+((size_t)e*TOK+m0+row)*DDIM+dbase+d0;
        #pragma unroll
        for(int j=0;j<32;j+=8){
            unsigned hv[4],lv[4];
            #pragma unroll
            for(int q=0;q<4;q++){
                float a=sv[row*68+d0+j+2*q], b=sv[row*68+d0+j+2*q+1];
                __nv_bfloat16 ha=__float2bfloat16_rn(a), hb=__float2bfloat16_rn(b);
                hv[q]=(unsigned)__bfloat16_as_ushort(ha)|((unsigned)__bfloat16_as_ushort(hb)<<16);
                __nv_bfloat16 la=__float2bfloat16_rn(a-__bfloat162float(ha));
                __nv_bfloat16 lb=__float2bfloat16_rn(b-__bfloat162float(hb));
                lv[q]=(unsigned)__bfloat16_as_ushort(la)|((unsigned)__bfloat16_as_ushort(lb)<<16);
            }
            *(uint4*)(oh+j)=make_uint4(hv[0],hv[1],hv[2],hv[3]);
            *(uint4*)(ol+j)=make_uint4(lv[0],lv[1],lv[2],lv[3]);
        }
    }
}

// ======================= GEMM2: down proj + bias + expert sum =======================
// CTA tile: 128 tokens x 96 h. 256 thr, warps 4m x 2n (32x48). K = 8*2880.
#define S2_ALO 10240
#define S2_B   20480
#define S2_BLO 6656
#define S2_STAGE 33792

__global__ __launch_bounds__(256,1)
void gemm2_kernel(const float* __restrict__ rw, const float* __restrict__ bd,
                  float* __restrict__ out)
{
    extern __shared__ __align__(16) char dsm[];
    __shared__ float sRw[128*8];
    const int tid=threadIdx.x, lane=tid&31, w=tid>>5;
    const int m0=blockIdx.y*128, h0=blockIdx.x*96;
    const unsigned db=su32(dsm);
    for(int i=tid;i<1024;i+=256) sRw[i]=rw[(size_t)(m0+(i>>3))*NEXP+(i&7)];

    const int ar=tid>>2, ac=tid&3;

    auto LOAD=[&](int kc,int s){
        const int e=kc/90, kl=(kc-e*90)*32;
        const unsigned st=db+(unsigned)s*S2_STAGE;
        const __nv_bfloat16* ah=g_a_hi+((size_t)e*TOK+m0)*DDIM+kl;
        const __nv_bfloat16* al=g_a_lo+((size_t)e*TOK+m0)*DDIM+kl;
        cpa16(st+ar*80+ac*16,            ah+(size_t)ar*DDIM+ac*8);
        cpa16(st+(ar+64)*80+ac*16,       ah+(size_t)(ar+64)*DDIM+ac*8);
        cpa16(st+S2_ALO+ar*80+ac*16,     al+(size_t)ar*DDIM+ac*8);
        cpa16(st+S2_ALO+(ar+64)*80+ac*16,al+(size_t)(ar+64)*DDIM+ac*8);
        const __nv_bfloat16* bh=g_wd_hi+((size_t)e*DDIM+kl)*HDIM+h0;
        const __nv_bfloat16* bl=g_wd_lo+((size_t)e*DDIM+kl)*HDIM+h0;
        #pragma unroll
        for(int i=0;i<2;i++){
            int ch=tid+256*i;
            if(ch<384){
                int r=ch/12, c=ch-r*12;
                cpa16(st+S2_B+r*208+c*16,        bh+(size_t)r*HDIM+c*8);
                cpa16(st+S2_B+S2_BLO+r*208+c*16, bl+(size_t)r*HDIM+c*8);
            }
        }
        cpcommit();
    };

    const int mw=(w&3)*32, nw=(w>>2)*48;
    float C[2][6][4];
    #pragma unroll
    for(int i=0;i<2;i++)
        #pragma unroll
        for(int j=0;j<6;j++)
            #pragma unroll
            for(int q=0;q<4;q++) C[i][j][q]=0.f;

    LOAD(0,0); LOAD(1,1);
    const int NCH=NEXP*90; // 720
    for(int kc=0;kc<NCH;kc++){
        if(kc==NCH-1) cpwait<0>(); else cpwait<1>();
        __syncthreads();
        if(kc+2<NCH) LOAD(kc+2,(kc+2)%3);
        const unsigned ab=db+(unsigned)(kc%3)*S2_STAGE;
        #pragma unroll
        for(int ks=0;ks<2;ks++){
            unsigned a_h[2][4],a_l[2][4],b_h[6][2],b_l[6][2];
            const unsigned abase=ab+(mw+(lane&15))*80+((lane>>4)*16)+ks*32;
            #pragma unroll
            for(int mt=0;mt<2;mt++){
                ldsm4(a_h[mt],abase+mt*16*80);
                ldsm4(a_l[mt],abase+S2_ALO+mt*16*80);
            }
            const unsigned bbase=ab+S2_B+(ks*16+(lane&15))*208;
            #pragma unroll
            for(int nt=0;nt<6;nt++){
                unsigned o=bbase+(nw+nt*8)*2;
                ldsm2t(b_h[nt],o);
                ldsm2t(b_l[nt],o+S2_BLO);
            }
            #pragma unroll
            for(int mt=0;mt<2;mt++)
                #pragma unroll
                for(int nt=0;nt<6;nt++){
                    mma_bf(C[mt][nt],a_h[mt],b_h[nt]);
                    mma_bf(C[mt][nt],a_h[mt],b_l[nt]);
                    mma_bf(C[mt][nt],a_l[mt],b_h[nt]);
                }
        }
    }

    // epilogue: + sum_e rw*bd, write fp32 out
    const int grp=lane>>2, tq=lane&3;
    #pragma unroll
    for(int nt=0;nt<6;nt++){
        const int col=h0+nw+nt*8+tq*2;
        float bd0[NEXP], bd1[NEXP];
        #pragma unroll
        for(int e2=0;e2<NEXP;e2++){
            bd0[e2]=bd[(size_t)e2*HDIM+col];
            bd1[e2]=bd[(size_t)e2*HDIM+col+1];
        }
        #pragma unroll
        for(int mt=0;mt<2;mt++)
            #pragma unroll
            for(int h=0;h<2;h++){
                const int row=mw+mt*16+grp+h*8;
                float v0=C[mt][nt][2*h], v1=C[mt][nt][2*h+1];
                #pragma unroll
                for(int e2=0;e2<NEXP;e2++){
                    float r=sRw[row*8+e2];
                    v0=fmaf(r,bd0[e2],v0);
                    v1=fmaf(r,bd1[e2],v1);
                }
                float2 t; t.x=v0; t.y=v1;
                *(float2*)(out+(size_t)(m0+row)*HDIM+col)=t;
            }
    }
}

extern "C" void kernel_launch(void* const* d_in, const int* in_sizes, int n_in,
                              void* d_out, int out_size)
{
    const float* x  =(const float*)d_in[0];
    const float* rw =(const float*)d_in[1];
    const float* wgu=(const float*)d_in[2];
    const float* bgu=(const float*)d_in[3];
    const float* wd =(const float*)d_in[4];
    const float* bd =(const float*)d_in[5];
    float* out=(float*)d_out;

    cudaFuncSetAttribute(gemm1_kernel, cudaFuncAttributeMaxDynamicSharedMemorySize, 3*S1_STAGE);
    cudaFuncSetAttribute(gemm2_kernel, cudaFuncAttributeMaxDynamicSharedMemorySize, 3*S2_STAGE);

    split_kernel<<<592,256>>>((const float4*)x,  0, (long long)TOK*HDIM/4);
    split_kernel<<<592,256>>>((const float4*)wgu,1, (long long)NEXP*HDIM*GUCOLS/4);
    split_kernel<<<592,256>>>((const float4*)wd, 2, (long long)NEXP*DDIM*HDIM/4);
    gemm1_kernel<<<dim3(45,8,NEXP),256,3*S1_STAGE>>>(rw,bgu);
    gemm2_kernel<<<dim3(30,8),256,3*S2_STAGE>>>(rw,bd,out);
}

// round 5
// speedup vs baseline: 2.7459x; 1.1468x over previous
#include <cuda_runtime.h>
#include <cuda_bf16.h>
#include <math.h>

#define TOK 1024
#define HDIM 2880
#define DDIM 2880
#define NEXP 8
#define GUCOLS 5760
#define ALPHA 1.702f
#define LIMIT 7.0f

__device__ __align__(16) __nv_bfloat16 g_wgu_hi[(size_t)NEXP*HDIM*GUCOLS];
__device__ __align__(16) __nv_bfloat16 g_wgu_lo[(size_t)NEXP*HDIM*GUCOLS];
__device__ __align__(16) __nv_bfloat16 g_wd_hi[(size_t)NEXP*DDIM*HDIM];
__device__ __align__(16) __nv_bfloat16 g_wd_lo[(size_t)NEXP*DDIM*HDIM];
__device__ __align__(16) __nv_bfloat16 g_x_hi[(size_t)TOK*HDIM];
__device__ __align__(16) __nv_bfloat16 g_x_lo[(size_t)TOK*HDIM];
__device__ __align__(16) __nv_bfloat16 g_a_hi[(size_t)NEXP*TOK*DDIM];
__device__ __align__(16) __nv_bfloat16 g_a_lo[(size_t)NEXP*TOK*DDIM];

__device__ __forceinline__ unsigned su32(const void* p){
    unsigned a; asm("{ .reg .u64 t; cvta.to.shared.u64 t, %1; cvt.u32.u64 %0, t; }":"=r"(a):"l"(p)); return a;
}
template<int N> __device__ __forceinline__ void cpwait(){
    asm volatile("cp.async.wait_group %0;"::"n"(N):"memory");
}
__device__ __forceinline__ void cpcommit(){
    asm volatile("cp.async.commit_group;":::"memory");
}
__device__ __forceinline__ void cpa16(unsigned d, const void* s){
    asm volatile("cp.async.cg.shared.global [%0], [%1], 16;"::"r"(d),"l"(s):"memory");
}
__device__ __forceinline__ void ldsm4(unsigned* r, unsigned a){
    asm volatile("ldmatrix.sync.aligned.m8n8.x4.shared.b16 {%0,%1,%2,%3}, [%4];"
        :"=r"(r[0]),"=r"(r[1]),"=r"(r[2]),"=r"(r[3]):"r"(a));
}
__device__ __forceinline__ void ldsm2t(unsigned* r, unsigned a){
    asm volatile("ldmatrix.sync.aligned.m8n8.x2.trans.shared.b16 {%0,%1}, [%2];"
        :"=r"(r[0]),"=r"(r[1]):"r"(a));
}
__device__ __forceinline__ void mma_bf(float* c, const unsigned* a, const unsigned* b){
    asm volatile("mma.sync.aligned.m16n8k16.row.col.f32.bf16.bf16.f32 "
        "{%0,%1,%2,%3},{%4,%5,%6,%7},{%8,%9},{%0,%1,%2,%3};"
        : "+f"(c[0]),"+f"(c[1]),"+f"(c[2]),"+f"(c[3])
        : "r"(a[0]),"r"(a[1]),"r"(a[2]),"r"(a[3]),"r"(b[0]),"r"(b[1]));
}

// -------- fp32 -> bf16 hi/lo split --------
__global__ void split_kernel(const float4* __restrict__ src, int which, long long n4){
    __nv_bfloat16 *hi, *lo;
    if(which==0){hi=g_x_hi;lo=g_x_lo;} else if(which==1){hi=g_wgu_hi;lo=g_wgu_lo;} else {hi=g_wd_hi;lo=g_wd_lo;}
    uint2* hp=(uint2*)hi; uint2* lp=(uint2*)lo;
    long long i=(long long)blockIdx.x*blockDim.x+threadIdx.x, st=(long long)gridDim.x*blockDim.x;
    for(; i<n4; i+=st){
        float4 f=src[i];
        __nv_bfloat16 h0=__float2bfloat16_rn(f.x), h1=__float2bfloat16_rn(f.y);
        __nv_bfloat16 h2=__float2bfloat16_rn(f.z), h3=__float2bfloat16_rn(f.w);
        __nv_bfloat16 l0=__float2bfloat16_rn(f.x-__bfloat162float(h0));
        __nv_bfloat16 l1=__float2bfloat16_rn(f.y-__bfloat162float(h1));
        __nv_bfloat16 l2=__float2bfloat16_rn(f.z-__bfloat162float(h2));
        __nv_bfloat16 l3=__float2bfloat16_rn(f.w-__bfloat162float(h3));
        uint2 hv, lv;
        hv.x=(unsigned)__bfloat16_as_ushort(h0)|((unsigned)__bfloat16_as_ushort(h1)<<16);
        hv.y=(unsigned)__bfloat16_as_ushort(h2)|((unsigned)__bfloat16_as_ushort(h3)<<16);
        lv.x=(unsigned)__bfloat16_as_ushort(l0)|((unsigned)__bfloat16_as_ushort(l1)<<16);
        lv.y=(unsigned)__bfloat16_as_ushort(l2)|((unsigned)__bfloat16_as_ushort(l3)<<16);
        hp[i]=hv; lp[i]=lv;
    }
}

// ======================= GEMM1: gate_up + SwiGLU =======================
// CTA tile: 128 tokens x 128 gu-cols. 256 thr, warps 2m x 4n (64x32).
// 2-stage double buffer, 2 CTAs/SM.
#define S1_ALO 10240
#define S1_B   20480
#define S1_BLO 8704
#define S1_STAGE 37888

__global__ __launch_bounds__(256,2)
void gemm1_kernel(const float* __restrict__ rw, const float* __restrict__ bgu)
{
    extern __shared__ __align__(16) char dsm[];
    __shared__ float sBias[128];
    __shared__ float sRw[128];
    const int tid=threadIdx.x, lane=tid&31, w=tid>>5;
    const int e=blockIdx.z, m0=blockIdx.y*128, c0=blockIdx.x*128, dbase=blockIdx.x*64;
    const unsigned db=su32(dsm);
    if(tid<128){
        sBias[tid]=bgu[(size_t)e*GUCOLS+c0+tid];
        sRw[tid]=rw[(size_t)(m0+tid)*NEXP+e];
    }

    const __nv_bfloat16* xh = g_x_hi + (size_t)m0*HDIM;
    const __nv_bfloat16* xl = g_x_lo + (size_t)m0*HDIM;
    const __nv_bfloat16* wh = g_wgu_hi + (size_t)e*HDIM*GUCOLS + c0;
    const __nv_bfloat16* wl = g_wgu_lo + (size_t)e*HDIM*GUCOLS + c0;

    const int ar=tid>>2, ac=tid&3;
    const int br=tid>>4, bc=tid&15;

    auto LOAD=[&](int kc,int s){
        const unsigned st=db+(unsigned)s*S1_STAGE;
        const int k0=kc*32;
        cpa16(st+ar*80+ac*16,            xh+(size_t)ar*HDIM+k0+ac*8);
        cpa16(st+(ar+64)*80+ac*16,       xh+(size_t)(ar+64)*HDIM+k0+ac*8);
        cpa16(st+S1_ALO+ar*80+ac*16,     xl+(size_t)ar*HDIM+k0+ac*8);
        cpa16(st+S1_ALO+(ar+64)*80+ac*16,xl+(size_t)(ar+64)*HDIM+k0+ac*8);
        cpa16(st+S1_B+br*272+bc*16,            wh+(size_t)(k0+br)*GUCOLS+bc*8);
        cpa16(st+S1_B+(br+16)*272+bc*16,       wh+(size_t)(k0+br+16)*GUCOLS+bc*8);
        cpa16(st+S1_B+S1_BLO+br*272+bc*16,     wl+(size_t)(k0+br)*GUCOLS+bc*8);
        cpa16(st+S1_B+S1_BLO+(br+16)*272+bc*16,wl+(size_t)(k0+br+16)*GUCOLS+bc*8);
        cpcommit();
    };

    const int mw=(w&1)*64, nw=(w>>1)*32;
    float C[4][4][4];
    #pragma unroll
    for(int i=0;i<4;i++)
        #pragma unroll
        for(int j=0;j<4;j++)
            #pragma unroll
            for(int q=0;q<4;q++) C[i][j][q]=0.f;

    LOAD(0,0);
    const int NCH=HDIM/32; // 90
    for(int kc=0;kc<NCH;kc++){
        cpwait<0>();
        __syncthreads();
        if(kc+1<NCH) LOAD(kc+1,(kc+1)&1);
        const unsigned ab=db+(unsigned)(kc&1)*S1_STAGE;
        const unsigned bb=ab+S1_B;
        #pragma unroll
        for(int ks=0;ks<2;ks++){
            unsigned a[4][4],b_h[4][2],b_l[4][2];
            const unsigned bbase=bb+(ks*16+(lane&15))*272;
            #pragma unroll
            for(int nt=0;nt<4;nt++){
                unsigned o=bbase+(nw+nt*8)*2;
                ldsm2t(b_h[nt],o);
                ldsm2t(b_l[nt],o+S1_BLO);
            }
            const unsigned abase=ab+(mw+(lane&15))*80+((lane>>4)*16)+ks*32;
            #pragma unroll
            for(int mt=0;mt<4;mt++) ldsm4(a[mt],abase+mt*16*80);
            #pragma unroll
            for(int mt=0;mt<4;mt++)
                #pragma unroll
                for(int nt=0;nt<4;nt++){
                    mma_bf(C[mt][nt],a[mt],b_h[nt]);
                    mma_bf(C[mt][nt],a[mt],b_l[nt]);
                }
            #pragma unroll
            for(int mt=0;mt<4;mt++) ldsm4(a[mt],abase+S1_ALO+mt*16*80);
            #pragma unroll
            for(int mt=0;mt<4;mt++)
                #pragma unroll
                for(int nt=0;nt<4;nt++)
                    mma_bf(C[mt][nt],a[mt],b_h[nt]);
        }
        __syncthreads();
    }

    // epilogue: bias + SwiGLU + rw -> sv (fp32), then split to act hi/lo
    float* sv=(float*)dsm;
    const int grp=lane>>2, tq=lane&3;
    #pragma unroll
    for(int mt=0;mt<4;mt++)
        #pragma unroll
        for(int nt=0;nt<4;nt++){
            const int colL=nw+nt*8+tq*2;
            const int d=(nw>>1)+nt*4+tq;
            #pragma unroll
            for(int h=0;h<2;h++){
                const int row=mw+mt*16+grp+h*8;
                float g=C[mt][nt][2*h]  +sBias[colL];
                float u=C[mt][nt][2*h+1]+sBias[colL+1];
                g=fminf(g,LIMIT);
                u=fminf(fmaxf(u,-LIMIT),LIMIT);
                float glu=g/(1.0f+__expf(-ALPHA*g));
                sv[row*68+d]=(u+1.0f)*glu*sRw[row];
            }
        }
    __syncthreads();
    {
        const int row=tid>>1, d0=(tid&1)*32;
        __nv_bfloat16* oh=g_a_hi+((size_t)e*TOK+m0+row)*DDIM+dbase+d0;
        __nv_bfloat16* ol=g_a_lo+((size_t)e*TOK+m0+row)*DDIM+dbase+d0;
        #pragma unroll
        for(int j=0;j<32;j+=8){
            unsigned hv[4],lv[4];
            #pragma unroll
            for(int q=0;q<4;q++){
                float aa=sv[row*68+d0+j+2*q], b=sv[row*68+d0+j+2*q+1];
                __nv_bfloat16 ha=__float2bfloat16_rn(aa), hb=__float2bfloat16_rn(b);
                hv[q]=(unsigned)__bfloat16_as_ushort(ha)|((unsigned)__bfloat16_as_ushort(hb)<<16);
                __nv_bfloat16 la=__float2bfloat16_rn(aa-__bfloat162float(ha));
                __nv_bfloat16 lb=__float2bfloat16_rn(b-__bfloat162float(hb));
                lv[q]=(unsigned)__bfloat16_as_ushort(la)|((unsigned)__bfloat16_as_ushort(lb)<<16);
            }
            *(uint4*)(oh+j)=make_uint4(hv[0],hv[1],hv[2],hv[3]);
            *(uint4*)(ol+j)=make_uint4(lv[0],lv[1],lv[2],lv[3]);
        }
    }
}

// ======================= GEMM2: down proj + bias + expert sum =======================
// CTA tile: 128 tokens x 96 h. 256 thr, warps 4m x 2n (32x48). K = 8*2880.
#define S2_ALO 10240
#define S2_B   20480
#define S2_BLO 6656
#define S2_STAGE 33792

__global__ __launch_bounds__(256,2)
void gemm2_kernel(const float* __restrict__ rw, const float* __restrict__ bd,
                  float* __restrict__ out)
{
    extern __shared__ __align__(16) char dsm[];
    __shared__ float sRw[128*8];
    const int tid=threadIdx.x, lane=tid&31, w=tid>>5;
    const int m0=blockIdx.y*128, h0=blockIdx.x*96;
    const unsigned db=su32(dsm);
    for(int i=tid;i<1024;i+=256) sRw[i]=rw[(size_t)(m0+(i>>3))*NEXP+(i&7)];

    const int ar=tid>>2, ac=tid&3;

    auto LOAD=[&](int kc,int s){
        const int e=kc/90, kl=(kc-e*90)*32;
        const unsigned st=db+(unsigned)s*S2_STAGE;
        const __nv_bfloat16* ah=g_a_hi+((size_t)e*TOK+m0)*DDIM+kl;
        const __nv_bfloat16* al=g_a_lo+((size_t)e*TOK+m0)*DDIM+kl;
        cpa16(st+ar*80+ac*16,            ah+(size_t)ar*DDIM+ac*8);
        cpa16(st+(ar+64)*80+ac*16,       ah+(size_t)(ar+64)*DDIM+ac*8);
        cpa16(st+S2_ALO+ar*80+ac*16,     al+(size_t)ar*DDIM+ac*8);
        cpa16(st+S2_ALO+(ar+64)*80+ac*16,al+(size_t)(ar+64)*DDIM+ac*8);
        const __nv_bfloat16* bh=g_wd_hi+((size_t)e*DDIM+kl)*HDIM+h0;
        const __nv_bfloat16* bl=g_wd_lo+((size_t)e*DDIM+kl)*HDIM+h0;
        #pragma unroll
        for(int i=0;i<2;i++){
            int ch=tid+256*i;
            if(ch<384){
                int r=ch/12, c=ch-r*12;
                cpa16(st+S2_B+r*208+c*16,        bh+(size_t)r*HDIM+c*8);
                cpa16(st+S2_B+S2_BLO+r*208+c*16, bl+(size_t)r*HDIM+c*8);
            }
        }
        cpcommit();
    };

    const int mw=(w&3)*32, nw=(w>>2)*48;
    float C[2][6][4];
    #pragma unroll
    for(int i=0;i<2;i++)
        #pragma unroll
        for(int j=0;j<6;j++)
            #pragma unroll
            for(int q=0;q<4;q++) C[i][j][q]=0.f;

    LOAD(0,0);
    const int NCH=NEXP*90; // 720
    for(int kc=0;kc<NCH;kc++){
        cpwait<0>();
        __syncthreads();
        if(kc+1<NCH) LOAD(kc+1,(kc+1)&1);
        const unsigned ab=db+(unsigned)(kc&1)*S2_STAGE;
        #pragma unroll
        for(int ks=0;ks<2;ks++){
            unsigned a[2][4],b_h[6][2],b_l[6][2];
            const unsigned bbase=ab+S2_B+(ks*16+(lane&15))*208;
            #pragma unroll
            for(int nt=0;nt<6;nt++){
                unsigned o=bbase+(nw+nt*8)*2;
                ldsm2t(b_h[nt],o);
                ldsm2t(b_l[nt],o+S2_BLO);
            }
            const unsigned abase=ab+(mw+(lane&15))*80+((lane>>4)*16)+ks*32;
            #pragma unroll
            for(int mt=0;mt<2;mt++) ldsm4(a[mt],abase+mt*16*80);
            #pragma unroll
            for(int mt=0;mt<2;mt++)
                #pragma unroll
                for(int nt=0;nt<6;nt++){
                    mma_bf(C[mt][nt],a[mt],b_h[nt]);
                    mma_bf(C[mt][nt],a[mt],b_l[nt]);
                }
            #pragma unroll
            for(int mt=0;mt<2;mt++) ldsm4(a[mt],abase+S2_ALO+mt*16*80);
            #pragma unroll
            for(int mt=0;mt<2;mt++)
                #pragma unroll
                for(int nt=0;nt<6;nt++)
                    mma_bf(C[mt][nt],a[mt],b_h[nt]);
        }
        __syncthreads();
    }

    // epilogue: + sum_e rw*bd, write fp32 out
    const int grp=lane>>2, tq=lane&3;
    #pragma unroll
    for(int nt=0;nt<6;nt++){
        const int col=h0+nw+nt*8+tq*2;
        #pragma unroll
        for(int mt=0;mt<2;mt++)
            #pragma unroll
            for(int h=0;h<2;h++){
                const int row=mw+mt*16+grp+h*8;
                float v0=C[mt][nt][2*h], v1=C[mt][nt][2*h+1];
                #pragma unroll
                for(int e2=0;e2<NEXP;e2++){
                    float r=sRw[row*8+e2];
                    v0=fmaf(r,bd[(size_t)e2*HDIM+col],v0);
                    v1=fmaf(r,bd[(size_t)e2*HDIM+col+1],v1);
                }
                float2 t; t.x=v0; t.y=v1;
                *(float2*)(out+(size_t)(m0+row)*HDIM+col)=t;
            }
    }
}

extern "C" void kernel_launch(void* const* d_in, const int* in_sizes, int n_in,
                              void* d_out, int out_size)
{
    const float* x  =(const float*)d_in[0];
    const float* rw =(const float*)d_in[1];
    const float* wgu=(const float*)d_in[2];
    const float* bgu=(const float*)d_in[3];
    const float* wd =(const float*)d_in[4];
    const float* bd =(const float*)d_in[5];
    float* out=(float*)d_out;

    cudaFuncSetAttribute(gemm1_kernel, cudaFuncAttributeMaxDynamicSharedMemorySize, 2*S1_STAGE);
    cudaFuncSetAttribute(gemm2_kernel, cudaFuncAttributeMaxDynamicSharedMemorySize, 2*S2_STAGE);

    split_kernel<<<592,256>>>((const float4*)x,  0, (long long)TOK*HDIM/4);
    split_kernel<<<592,256>>>((const float4*)wgu,1, (long long)NEXP*HDIM*GUCOLS/4);
    split_kernel<<<592,256>>>((const float4*)wd, 2, (long long)NEXP*DDIM*HDIM/4);
    gemm1_kernel<<<dim3(45,8,NEXP),256,2*S1_STAGE>>>(rw,bgu);
    gemm2_kernel<<<dim3(30,8),256,2*S2_STAGE>>>(rw,bd,out);
}

// round 6
// speedup vs baseline: 3.0923x; 1.1262x over previous
#include <cuda_runtime.h>
#include <cuda_bf16.h>
#include <math.h>

#define TOK 1024
#define HDIM 2880
#define DDIM 2880
#define NEXP 8
#define GUCOLS 5760
#define ALPHA 1.702f
#define LIMIT 7.0f

__device__ __align__(16) __nv_bfloat16 g_wgu_hi[(size_t)NEXP*HDIM*GUCOLS];
__device__ __align__(16) __nv_bfloat16 g_wgu_lo[(size_t)NEXP*HDIM*GUCOLS];
__device__ __align__(16) __nv_bfloat16 g_wd_hi[(size_t)NEXP*DDIM*HDIM];
__device__ __align__(16) __nv_bfloat16 g_wd_lo[(size_t)NEXP*DDIM*HDIM];
__device__ __align__(16) __nv_bfloat16 g_x_hi[(size_t)TOK*HDIM];
__device__ __align__(16) __nv_bfloat16 g_x_lo[(size_t)TOK*HDIM];
__device__ __align__(16) __nv_bfloat16 g_a_hi[(size_t)NEXP*TOK*DDIM];
__device__ __align__(16) __nv_bfloat16 g_a_lo[(size_t)NEXP*TOK*DDIM];

__device__ __forceinline__ unsigned su32(const void* p){
    unsigned a; asm("{ .reg .u64 t; cvta.to.shared.u64 t, %1; cvt.u32.u64 %0, t; }":"=r"(a):"l"(p)); return a;
}
template<int N> __device__ __forceinline__ void cpwait(){
    asm volatile("cp.async.wait_group %0;"::"n"(N):"memory");
}
__device__ __forceinline__ void cpcommit(){
    asm volatile("cp.async.commit_group;":::"memory");
}
__device__ __forceinline__ void cpa16(unsigned d, const void* s){
    asm volatile("cp.async.cg.shared.global [%0], [%1], 16;"::"r"(d),"l"(s):"memory");
}
__device__ __forceinline__ void ldsm4(unsigned* r, unsigned a){
    asm volatile("ldmatrix.sync.aligned.m8n8.x4.shared.b16 {%0,%1,%2,%3}, [%4];"
        :"=r"(r[0]),"=r"(r[1]),"=r"(r[2]),"=r"(r[3]):"r"(a));
}
__device__ __forceinline__ void ldsm2t(unsigned* r, unsigned a){
    asm volatile("ldmatrix.sync.aligned.m8n8.x2.trans.shared.b16 {%0,%1}, [%2];"
        :"=r"(r[0]),"=r"(r[1]):"r"(a));
}
__device__ __forceinline__ void mma_bf(float* c, const unsigned* a, const unsigned* b){
    asm volatile("mma.sync.aligned.m16n8k16.row.col.f32.bf16.bf16.f32 "
        "{%0,%1,%2,%3},{%4,%5,%6,%7},{%8,%9},{%0,%1,%2,%3};"
        : "+f"(c[0]),"+f"(c[1]),"+f"(c[2]),"+f"(c[3])
        : "r"(a[0]),"r"(a[1]),"r"(a[2]),"r"(a[3]),"r"(b[0]),"r"(b[1]));
}

// -------- fp32 -> bf16 hi/lo split --------
__global__ void split_kernel(const float4* __restrict__ src, int which, long long n4){
    __nv_bfloat16 *hi, *lo;
    if(which==0){hi=g_x_hi;lo=g_x_lo;} else if(which==1){hi=g_wgu_hi;lo=g_wgu_lo;} else {hi=g_wd_hi;lo=g_wd_lo;}
    uint2* hp=(uint2*)hi; uint2* lp=(uint2*)lo;
    long long i=(long long)blockIdx.x*blockDim.x+threadIdx.x, st=(long long)gridDim.x*blockDim.x;
    for(; i<n4; i+=st){
        float4 f=src[i];
        __nv_bfloat16 h0=__float2bfloat16_rn(f.x), h1=__float2bfloat16_rn(f.y);
        __nv_bfloat16 h2=__float2bfloat16_rn(f.z), h3=__float2bfloat16_rn(f.w);
        __nv_bfloat16 l0=__float2bfloat16_rn(f.x-__bfloat162float(h0));
        __nv_bfloat16 l1=__float2bfloat16_rn(f.y-__bfloat162float(h1));
        __nv_bfloat16 l2=__float2bfloat16_rn(f.z-__bfloat162float(h2));
        __nv_bfloat16 l3=__float2bfloat16_rn(f.w-__bfloat162float(h3));
        uint2 hv, lv;
        hv.x=(unsigned)__bfloat16_as_ushort(h0)|((unsigned)__bfloat16_as_ushort(h1)<<16);
        hv.y=(unsigned)__bfloat16_as_ushort(h2)|((unsigned)__bfloat16_as_ushort(h3)<<16);
        lv.x=(unsigned)__bfloat16_as_ushort(l0)|((unsigned)__bfloat16_as_ushort(l1)<<16);
        lv.y=(unsigned)__bfloat16_as_ushort(l2)|((unsigned)__bfloat16_as_ushort(l3)<<16);
        hp[i]=hv; lp[i]=lv;
    }
}

// ======================= GEMM1: gate_up + SwiGLU =======================
// CTA tile: 128 tokens x 128 gu-cols. 256 thr, warps 2m x 4n (64x32).
// Swizzled SMEM: A rows 64B (chunk ^= (row>>1)&3), B rows 256B (chunk ^= row&7).
// Stage 32KB, 3 stages, 2 CTAs/SM.
#define S1_STAGE 32768

__global__ __launch_bounds__(256,2)
void gemm1_kernel(const float* __restrict__ rw, const float* __restrict__ bgu)
{
    extern __shared__ __align__(16) char dsm[];
    __shared__ float sBias[128];
    __shared__ float sRw[128];
    const int tid=threadIdx.x, lane=tid&31, w=tid>>5;
    const int e=blockIdx.z, m0=blockIdx.y*128, c0=blockIdx.x*128, dbase=blockIdx.x*64;
    const unsigned db=su32(dsm);
    if(tid<128){
        sBias[tid]=bgu[(size_t)e*GUCOLS+c0+tid];
        sRw[tid]=rw[(size_t)(m0+tid)*NEXP+e];
    }

    const __nv_bfloat16* xh = g_x_hi + (size_t)m0*HDIM;
    const __nv_bfloat16* xl = g_x_lo + (size_t)m0*HDIM;
    const __nv_bfloat16* wh = g_wgu_hi + (size_t)e*HDIM*GUCOLS + c0;
    const __nv_bfloat16* wl = g_wgu_lo + (size_t)e*HDIM*GUCOLS + c0;

    const int ar=tid>>2, ac=tid&3;
    const int br=tid>>4, bc=tid&15;
    const unsigned a_off = (unsigned)ar*64 + (unsigned)((ac ^ ((ar>>1)&3))*16);
    const unsigned b_off = (unsigned)br*256 + (unsigned)((bc ^ (br&7))*16);

    auto LOAD=[&](int kc,int s){
        const unsigned st=db+(unsigned)s*S1_STAGE;
        const int k0=kc*32;
        cpa16(st+a_off,            xh+(size_t)ar*HDIM+k0+ac*8);
        cpa16(st+4096+a_off,       xh+(size_t)(ar+64)*HDIM+k0+ac*8);
        cpa16(st+8192+a_off,       xl+(size_t)ar*HDIM+k0+ac*8);
        cpa16(st+12288+a_off,      xl+(size_t)(ar+64)*HDIM+k0+ac*8);
        cpa16(st+16384+b_off,      wh+(size_t)(k0+br)*GUCOLS+bc*8);
        cpa16(st+20480+b_off,      wh+(size_t)(k0+br+16)*GUCOLS+bc*8);
        cpa16(st+24576+b_off,      wl+(size_t)(k0+br)*GUCOLS+bc*8);
        cpa16(st+28672+b_off,      wl+(size_t)(k0+br+16)*GUCOLS+bc*8);
        cpcommit();
    };

    const int mw=(w&1)*64, nw=(w>>1)*32;
    float C[4][4][4];
    #pragma unroll
    for(int i=0;i<4;i++)
        #pragma unroll
        for(int j=0;j<4;j++)
            #pragma unroll
            for(int q=0;q<4;q++) C[i][j][q]=0.f;

    // per-lane fragment address pieces (swizzles are invariant across mt/+16 rows)
    const int rl=lane&15;
    const unsigned aswz=((rl>>1)&3);
    const unsigned bswz=(lane&7);

    LOAD(0,0); LOAD(1,1);
    const int NCH=HDIM/32; // 90
    for(int kc=0;kc<NCH;kc++){
        if(kc==NCH-1) cpwait<0>(); else cpwait<1>();
        __syncthreads();
        if(kc+2<NCH) LOAD(kc+2,(kc+2)%3);
        const unsigned ab=db+(unsigned)(kc%3)*S1_STAGE;
        const unsigned bb=ab+16384;
        #pragma unroll
        for(int ks=0;ks<2;ks++){
            unsigned a[4][4],b_h[4][2],b_l[4][2];
            const unsigned boff=bb+(unsigned)(ks*16+rl)*256;
            #pragma unroll
            for(int nt=0;nt<4;nt++){
                unsigned o=boff+((((nw>>3)+nt)^bswz)*16);
                ldsm2t(b_h[nt],o);
                ldsm2t(b_l[nt],o+8192);
            }
            const unsigned aoff=ab+(unsigned)(mw+rl)*64+((((lane>>4)+ks*2)^aswz)*16);
            #pragma unroll
            for(int mt=0;mt<4;mt++) ldsm4(a[mt],aoff+mt*1024);
            #pragma unroll
            for(int mt=0;mt<4;mt++)
                #pragma unroll
                for(int nt=0;nt<4;nt++)
                    mma_bf(C[mt][nt],a[mt],b_h[nt]);
            #pragma unroll
            for(int mt=0;mt<4;mt++)
                #pragma unroll
                for(int nt=0;nt<4;nt++)
                    mma_bf(C[mt][nt],a[mt],b_l[nt]);
            #pragma unroll
            for(int mt=0;mt<4;mt++) ldsm4(a[mt],aoff+8192+mt*1024);
            #pragma unroll
            for(int mt=0;mt<4;mt++)
                #pragma unroll
                for(int nt=0;nt<4;nt++)
                    mma_bf(C[mt][nt],a[mt],b_h[nt]);
        }
    }
    __syncthreads();

    // epilogue: bias + SwiGLU + rw -> sv (fp32), then split to act hi/lo
    float* sv=(float*)dsm;
    const int grp=lane>>2, tq=lane&3;
    #pragma unroll
    for(int mt=0;mt<4;mt++)
        #pragma unroll
        for(int nt=0;nt<4;nt++){
            const int colL=nw+nt*8+tq*2;
            const int d=(nw>>1)+nt*4+tq;
            #pragma unroll
            for(int h=0;h<2;h++){
                const int row=mw+mt*16+grp+h*8;
                float g=C[mt][nt][2*h]  +sBias[colL];
                float u=C[mt][nt][2*h+1]+sBias[colL+1];
                g=fminf(g,LIMIT);
                u=fminf(fmaxf(u,-LIMIT),LIMIT);
                float glu=g/(1.0f+__expf(-ALPHA*g));
                sv[row*68+d]=(u+1.0f)*glu*sRw[row];
            }
        }
    __syncthreads();
    {
        const int row=tid>>1, d0=(tid&1)*32;
        __nv_bfloat16* oh=g_a_hi+((size_t)e*TOK+m0+row)*DDIM+dbase+d0;
        __nv_bfloat16* ol=g_a_lo+((size_t)e*TOK+m0+row)*DDIM+dbase+d0;
        #pragma unroll
        for(int j=0;j<32;j+=8){
            unsigned hv[4],lv[4];
            #pragma unroll
            for(int q=0;q<4;q++){
                float aa=sv[row*68+d0+j+2*q], b=sv[row*68+d0+j+2*q+1];
                __nv_bfloat16 ha=__float2bfloat16_rn(aa), hb=__float2bfloat16_rn(b);
                hv[q]=(unsigned)__bfloat16_as_ushort(ha)|((unsigned)__bfloat16_as_ushort(hb)<<16);
                __nv_bfloat16 la=__float2bfloat16_rn(aa-__bfloat162float(ha));
                __nv_bfloat16 lb=__float2bfloat16_rn(b-__bfloat162float(hb));
                lv[q]=(unsigned)__bfloat16_as_ushort(la)|((unsigned)__bfloat16_as_ushort(lb)<<16);
            }
            *(uint4*)(oh+j)=make_uint4(hv[0],hv[1],hv[2],hv[3]);
            *(uint4*)(ol+j)=make_uint4(lv[0],lv[1],lv[2],lv[3]);
        }
    }
}

// ======================= GEMM2: down proj + bias + expert sum =======================
// CTA tile: 128 tokens x 96 h. 256 thr, warps 4m x 2n (32x48). K = 8*2880.
// A swizzled 64B rows; B padded 208B stride. Stage 29696, 3 stages, 2 CTAs/SM.
#define S2_BHI 16384
#define S2_BLO 23040
#define S2_STAGE 29696

__global__ __launch_bounds__(256,2)
void gemm2_kernel(const float* __restrict__ rw, const float* __restrict__ bd,
                  float* __restrict__ out)
{
    extern __shared__ __align__(16) char dsm[];
    __shared__ float sRw[128*8];
    const int tid=threadIdx.x, lane=tid&31, w=tid>>5;
    const int m0=blockIdx.y*128, h0=blockIdx.x*96;
    const unsigned db=su32(dsm);
    for(int i=tid;i<1024;i+=256) sRw[i]=rw[(size_t)(m0+(i>>3))*NEXP+(i&7)];

    const int ar=tid>>2, ac=tid&3;
    const unsigned a_off = (unsigned)ar*64 + (unsigned)((ac ^ ((ar>>1)&3))*16);

    auto LOAD=[&](int kc,int s){
        const int e=kc/90, kl=(kc-e*90)*32;
        const unsigned st=db+(unsigned)s*S2_STAGE;
        const __nv_bfloat16* ah=g_a_hi+((size_t)e*TOK+m0)*DDIM+kl;
        const __nv_bfloat16* al=g_a_lo+((size_t)e*TOK+m0)*DDIM+kl;
        cpa16(st+a_off,       ah+(size_t)ar*DDIM+ac*8);
        cpa16(st+4096+a_off,  ah+(size_t)(ar+64)*DDIM+ac*8);
        cpa16(st+8192+a_off,  al+(size_t)ar*DDIM+ac*8);
        cpa16(st+12288+a_off, al+(size_t)(ar+64)*DDIM+ac*8);
        const __nv_bfloat16* bh=g_wd_hi+((size_t)e*DDIM+kl)*HDIM+h0;
        const __nv_bfloat16* bl=g_wd_lo+((size_t)e*DDIM+kl)*HDIM+h0;
        #pragma unroll
        for(int i=0;i<2;i++){
            int ch=tid+256*i;
            if(ch<384){
                int r=ch/12, c=ch-r*12;
                cpa16(st+S2_BHI+r*208+c*16, bh+(size_t)r*HDIM+c*8);
                cpa16(st+S2_BLO+r*208+c*16, bl+(size_t)r*HDIM+c*8);
            }
        }
        cpcommit();
    };

    const int mw=(w&3)*32, nw=(w>>2)*48;
    float C[2][6][4];
    #pragma unroll
    for(int i=0;i<2;i++)
        #pragma unroll
        for(int j=0;j<6;j++)
            #pragma unroll
            for(int q=0;q<4;q++) C[i][j][q]=0.f;

    const int rl=lane&15;
    const unsigned aswz=((rl>>1)&3);

    LOAD(0,0); LOAD(1,1);
    const int NCH=NEXP*90; // 720
    for(int kc=0;kc<NCH;kc++){
        if(kc==NCH-1) cpwait<0>(); else cpwait<1>();
        __syncthreads();
        if(kc+2<NCH) LOAD(kc+2,(kc+2)%3);
        const unsigned ab=db+(unsigned)(kc%3)*S2_STAGE;
        #pragma unroll
        for(int ks=0;ks<2;ks++){
            unsigned a[2][4],b_h[6][2],b_l[6][2];
            const unsigned bbase=ab+S2_BHI+(unsigned)(ks*16+rl)*208;
            #pragma unroll
            for(int nt=0;nt<6;nt++){
                unsigned o=bbase+(nw+nt*8)*2;
                ldsm2t(b_h[nt],o);
                ldsm2t(b_l[nt],o+(S2_BLO-S2_BHI));
            }
            const unsigned aoff=ab+(unsigned)(mw+rl)*64+((((lane>>4)+ks*2)^aswz)*16);
            #pragma unroll
            for(int mt=0;mt<2;mt++) ldsm4(a[mt],aoff+mt*1024);
            #pragma unroll
            for(int mt=0;mt<2;mt++)
                #pragma unroll
                for(int nt=0;nt<6;nt++)
                    mma_bf(C[mt][nt],a[mt],b_h[nt]);
            #pragma unroll
            for(int mt=0;mt<2;mt++)
                #pragma unroll
                for(int nt=0;nt<6;nt++)
                    mma_bf(C[mt][nt],a[mt],b_l[nt]);
            #pragma unroll
            for(int mt=0;mt<2;mt++) ldsm4(a[mt],aoff+8192+mt*1024);
            #pragma unroll
            for(int mt=0;mt<2;mt++)
                #pragma unroll
                for(int nt=0;nt<6;nt++)
                    mma_bf(C[mt][nt],a[mt],b_h[nt]);
        }
    }

    // epilogue: + sum_e rw*bd, write fp32 out
    const int grp=lane>>2, tq=lane&3;
    #pragma unroll
    for(int nt=0;nt<6;nt++){
        const int col=h0+nw+nt*8+tq*2;
        #pragma unroll
        for(int mt=0;mt<2;mt++)
            #pragma unroll
            for(int h=0;h<2;h++){
                const int row=mw+mt*16+grp+h*8;
                float v0=C[mt][nt][2*h], v1=C[mt][nt][2*h+1];
                #pragma unroll
                for(int e2=0;e2<NEXP;e2++){
                    float r=sRw[row*8+e2];
                    v0=fmaf(r,bd[(size_t)e2*HDIM+col],v0);
                    v1=fmaf(r,bd[(size_t)e2*HDIM+col+1],v1);
                }
                float2 t; t.x=v0; t.y=v1;
                *(float2*)(out+(size_t)(m0+row)*HDIM+col)=t;
            }
    }
}

extern "C" void kernel_launch(void* const* d_in, const int* in_sizes, int n_in,
                              void* d_out, int out_size)
{
    const float* x  =(const float*)d_in[0];
    const float* rw =(const float*)d_in[1];
    const float* wgu=(const float*)d_in[2];
    const float* bgu=(const float*)d_in[3];
    const float* wd =(const float*)d_in[4];
    const float* bd =(const float*)d_in[5];
    float* out=(float*)d_out;

    cudaFuncSetAttribute(gemm1_kernel, cudaFuncAttributeMaxDynamicSharedMemorySize, 3*S1_STAGE);
    cudaFuncSetAttribute(gemm2_kernel, cudaFuncAttributeMaxDynamicSharedMemorySize, 3*S2_STAGE);

    split_kernel<<<592,256>>>((const float4*)x,  0, (long long)TOK*HDIM/4);
    split_kernel<<<592,256>>>((const float4*)wgu,1, (long long)NEXP*HDIM*GUCOLS/4);
    split_kernel<<<592,256>>>((const float4*)wd, 2, (long long)NEXP*DDIM*HDIM/4);
    gemm1_kernel<<<dim3(45,8,NEXP),256,3*S1_STAGE>>>(rw,bgu);
    gemm2_kernel<<<dim3(30,8),256,3*S2_STAGE>>>(rw,bd,out);
}

// round 7
// speedup vs baseline: 4.5183x; 1.4611x over previous
#include <cuda_runtime.h>
#include <cuda_fp16.h>
#include <math.h>

#define TOK 1024
#define HDIM 2880
#define DDIM 2880
#define NEXP 8
#define GUCOLS 5760
#define ALPHA 1.702f
#define LIMIT 7.0f

__device__ __align__(16) __half g_wgu_h[(size_t)NEXP*HDIM*GUCOLS];
__device__ __align__(16) __half g_wd_h [(size_t)NEXP*DDIM*HDIM];
__device__ __align__(16) __half g_x_h  [(size_t)TOK*HDIM];
__device__ __align__(16) __half g_x_l  [(size_t)TOK*HDIM];
__device__ __align__(16) __half g_a_h  [(size_t)NEXP*TOK*DDIM];
__device__ __align__(16) __half g_a_l  [(size_t)NEXP*TOK*DDIM];

__device__ __forceinline__ unsigned su32(const void* p){
    unsigned a; asm("{ .reg .u64 t; cvta.to.shared.u64 t, %1; cvt.u32.u64 %0, t; }":"=r"(a):"l"(p)); return a;
}
template<int N> __device__ __forceinline__ void cpwait(){
    asm volatile("cp.async.wait_group %0;"::"n"(N):"memory");
}
__device__ __forceinline__ void cpcommit(){
    asm volatile("cp.async.commit_group;":::"memory");
}
__device__ __forceinline__ void cpa16(unsigned d, const void* s){
    asm volatile("cp.async.cg.shared.global [%0], [%1], 16;"::"r"(d),"l"(s):"memory");
}
__device__ __forceinline__ void ldsm4(unsigned* r, unsigned a){
    asm volatile("ldmatrix.sync.aligned.m8n8.x4.shared.b16 {%0,%1,%2,%3}, [%4];"
        :"=r"(r[0]),"=r"(r[1]),"=r"(r[2]),"=r"(r[3]):"r"(a));
}
__device__ __forceinline__ void ldsm2t(unsigned* r, unsigned a){
    asm volatile("ldmatrix.sync.aligned.m8n8.x2.trans.shared.b16 {%0,%1}, [%2];"
        :"=r"(r[0]),"=r"(r[1]):"r"(a));
}
__device__ __forceinline__ void mma_fp(float* c, const unsigned* a, const unsigned* b){
    asm volatile("mma.sync.aligned.m16n8k16.row.col.f32.f16.f16.f32 "
        "{%0,%1,%2,%3},{%4,%5,%6,%7},{%8,%9},{%0,%1,%2,%3};"
        : "+f"(c[0]),"+f"(c[1]),"+f"(c[2]),"+f"(c[3])
        : "r"(a[0]),"r"(a[1]),"r"(a[2]),"r"(a[3]),"r"(b[0]),"r"(b[1]));
}

// -------- fp32 -> fp16 split: x gets hi+lo, weights get hi only --------
__global__ void split_kernel(const float4* __restrict__ src, int which, long long n4){
    __half *hi, *lo=0;
    if(which==0){hi=g_x_h;lo=g_x_l;} else if(which==1){hi=g_wgu_h;} else {hi=g_wd_h;}
    uint2* hp=(uint2*)hi; uint2* lp=(uint2*)lo;
    long long i=(long long)blockIdx.x*blockDim.x+threadIdx.x, st=(long long)gridDim.x*blockDim.x;
    for(; i<n4; i+=st){
        float4 f=src[i];
        __half h0=__float2half_rn(f.x), h1=__float2half_rn(f.y);
        __half h2=__float2half_rn(f.z), h3=__float2half_rn(f.w);
        uint2 hv;
        hv.x=(unsigned)__half_as_ushort(h0)|((unsigned)__half_as_ushort(h1)<<16);
        hv.y=(unsigned)__half_as_ushort(h2)|((unsigned)__half_as_ushort(h3)<<16);
        hp[i]=hv;
        if(lo){
            __half l0=__float2half_rn(f.x-__half2float(h0));
            __half l1=__float2half_rn(f.y-__half2float(h1));
            __half l2=__float2half_rn(f.z-__half2float(h2));
            __half l3=__float2half_rn(f.w-__half2float(h3));
            uint2 lv;
            lv.x=(unsigned)__half_as_ushort(l0)|((unsigned)__half_as_ushort(l1)<<16);
            lv.y=(unsigned)__half_as_ushort(l2)|((unsigned)__half_as_ushort(l3)<<16);
            lp[i]=lv;
        }
    }
}

// ======================= GEMM1: gate_up + SwiGLU =======================
// CTA tile: 128 tokens x 128 gu-cols. 256 thr, warps 2m x 4n (64x32).
// Stage 24KB (Ah 8K | Al 8K | Bh 8K), 4 stages, 2 CTAs/SM.
#define S1_STAGE 24576

__global__ __launch_bounds__(256,2)
void gemm1_kernel(const float* __restrict__ rw, const float* __restrict__ bgu)
{
    extern __shared__ __align__(16) char dsm[];
    __shared__ float sBias[128];
    __shared__ float sRw[128];
    const int tid=threadIdx.x, lane=tid&31, w=tid>>5;
    const int e=blockIdx.z, m0=blockIdx.y*128, c0=blockIdx.x*128, dbase=blockIdx.x*64;
    const unsigned db=su32(dsm);
    if(tid<128){
        sBias[tid]=bgu[(size_t)e*GUCOLS+c0+tid];
        sRw[tid]=rw[(size_t)(m0+tid)*NEXP+e];
    }

    const __half* xh = g_x_h + (size_t)m0*HDIM;
    const __half* xl = g_x_l + (size_t)m0*HDIM;
    const __half* wh = g_wgu_h + (size_t)e*HDIM*GUCOLS + c0;

    const int ar=tid>>2, ac=tid&3;
    const int br=tid>>4, bc=tid&15;
    const unsigned a_off = (unsigned)ar*64 + (unsigned)((ac ^ ((ar>>1)&3))*16);
    const unsigned b_off = (unsigned)br*256 + (unsigned)((bc ^ (br&7))*16);

    const int NCH=HDIM/32; // 90
    auto LOAD=[&](int kc){
        if(kc<NCH){
            const unsigned st=db+(unsigned)(kc&3)*S1_STAGE;
            const int k0=kc*32;
            cpa16(st+a_off,       xh+(size_t)ar*HDIM+k0+ac*8);
            cpa16(st+4096+a_off,  xh+(size_t)(ar+64)*HDIM+k0+ac*8);
            cpa16(st+8192+a_off,  xl+(size_t)ar*HDIM+k0+ac*8);
            cpa16(st+12288+a_off, xl+(size_t)(ar+64)*HDIM+k0+ac*8);
            cpa16(st+16384+b_off, wh+(size_t)(k0+br)*GUCOLS+bc*8);
            cpa16(st+20480+b_off, wh+(size_t)(k0+br+16)*GUCOLS+bc*8);
        }
        cpcommit();
    };

    const int mw=(w&1)*64, nw=(w>>1)*32;
    float C[4][4][4];
    #pragma unroll
    for(int i=0;i<4;i++)
        #pragma unroll
        for(int j=0;j<4;j++)
            #pragma unroll
            for(int q=0;q<4;q++) C[i][j][q]=0.f;

    const int rl=lane&15;
    const unsigned aswz=((rl>>1)&3);
    const unsigned bswz=(lane&7);

    LOAD(0); LOAD(1); LOAD(2);
    for(int kc=0;kc<NCH;kc++){
        if(kc==NCH-1) cpwait<0>(); else cpwait<2>();
        __syncthreads();
        LOAD(kc+3);
        const unsigned ab=db+(unsigned)(kc&3)*S1_STAGE;
        const unsigned bb=ab+16384;
        #pragma unroll
        for(int ks=0;ks<2;ks++){
            unsigned a[4][4],b_h[4][2];
            const unsigned boff=bb+(unsigned)(ks*16+rl)*256;
            #pragma unroll
            for(int nt=0;nt<4;nt++)
                ldsm2t(b_h[nt],boff+((((nw>>3)+nt)^bswz)*16));
            const unsigned aoff=ab+(unsigned)(mw+rl)*64+((((lane>>4)+ks*2)^aswz)*16);
            #pragma unroll
            for(int mt=0;mt<4;mt++) ldsm4(a[mt],aoff+mt*1024);
            #pragma unroll
            for(int mt=0;mt<4;mt++)
                #pragma unroll
                for(int nt=0;nt<4;nt++)
                    mma_fp(C[mt][nt],a[mt],b_h[nt]);
            #pragma unroll
            for(int mt=0;mt<4;mt++) ldsm4(a[mt],aoff+8192+mt*1024);
            #pragma unroll
            for(int mt=0;mt<4;mt++)
                #pragma unroll
                for(int nt=0;nt<4;nt++)
                    mma_fp(C[mt][nt],a[mt],b_h[nt]);
        }
    }
    __syncthreads();

    // epilogue: bias + SwiGLU + rw -> sv (fp32), then split to act hi/lo
    float* sv=(float*)dsm;
    const int grp=lane>>2, tq=lane&3;
    #pragma unroll
    for(int mt=0;mt<4;mt++)
        #pragma unroll
        for(int nt=0;nt<4;nt++){
            const int colL=nw+nt*8+tq*2;
            const int d=(nw>>1)+nt*4+tq;
            #pragma unroll
            for(int h=0;h<2;h++){
                const int row=mw+mt*16+grp+h*8;
                float g=C[mt][nt][2*h]  +sBias[colL];
                float u=C[mt][nt][2*h+1]+sBias[colL+1];
                g=fminf(g,LIMIT);
                u=fminf(fmaxf(u,-LIMIT),LIMIT);
                float glu=g/(1.0f+__expf(-ALPHA*g));
                sv[row*68+d]=(u+1.0f)*glu*sRw[row];
            }
        }
    __syncthreads();
    {
        const int row=tid>>1, d0=(tid&1)*32;
        __half* oh=g_a_h+((size_t)e*TOK+m0+row)*DDIM+dbase+d0;
        __half* ol=g_a_l+((size_t)e*TOK+m0+row)*DDIM+dbase+d0;
        #pragma unroll
        for(int j=0;j<32;j+=8){
            unsigned hv[4],lv[4];
            #pragma unroll
            for(int q=0;q<4;q++){
                float aa=sv[row*68+d0+j+2*q], b=sv[row*68+d0+j+2*q+1];
                __half ha=__float2half_rn(aa), hb=__float2half_rn(b);
                hv[q]=(unsigned)__half_as_ushort(ha)|((unsigned)__half_as_ushort(hb)<<16);
                __half la=__float2half_rn(aa-__half2float(ha));
                __half lb=__float2half_rn(b-__half2float(hb));
                lv[q]=(unsigned)__half_as_ushort(la)|((unsigned)__half_as_ushort(lb)<<16);
            }
            *(uint4*)(oh+j)=make_uint4(hv[0],hv[1],hv[2],hv[3]);
            *(uint4*)(ol+j)=make_uint4(lv[0],lv[1],lv[2],lv[3]);
        }
    }
}

// ======================= GEMM2: down proj + bias + expert sum =======================
// CTA tile: 128 tokens x 96 h. 256 thr, warps 4m x 2n (32x48). K = 8*2880.
// Stage 23040 (Ah 8K | Al 8K | Bh 6.5K pad208), 4 stages, 2 CTAs/SM.
#define S2_BHI 16384
#define S2_STAGE 23040

__global__ __launch_bounds__(256,2)
void gemm2_kernel(const float* __restrict__ rw, const float* __restrict__ bd,
                  float* __restrict__ out)
{
    extern __shared__ __align__(16) char dsm[];
    __shared__ float sRw[128*8];
    const int tid=threadIdx.x, lane=tid&31, w=tid>>5;
    const int m0=blockIdx.y*128, h0=blockIdx.x*96;
    const unsigned db=su32(dsm);
    for(int i=tid;i<1024;i+=256) sRw[i]=rw[(size_t)(m0+(i>>3))*NEXP+(i&7)];

    const int ar=tid>>2, ac=tid&3;
    const unsigned a_off = (unsigned)ar*64 + (unsigned)((ac ^ ((ar>>1)&3))*16);

    const int NCH=NEXP*90; // 720
    auto LOAD=[&](int kc){
        if(kc<NCH){
            const int e=kc/90, kl=(kc-e*90)*32;
            const unsigned st=db+(unsigned)(kc&3)*S2_STAGE;
            const __half* ah=g_a_h+((size_t)e*TOK+m0)*DDIM+kl;
            const __half* al=g_a_l+((size_t)e*TOK+m0)*DDIM+kl;
            cpa16(st+a_off,       ah+(size_t)ar*DDIM+ac*8);
            cpa16(st+4096+a_off,  ah+(size_t)(ar+64)*DDIM+ac*8);
            cpa16(st+8192+a_off,  al+(size_t)ar*DDIM+ac*8);
            cpa16(st+12288+a_off, al+(size_t)(ar+64)*DDIM+ac*8);
            const __half* bh=g_wd_h+((size_t)e*DDIM+kl)*HDIM+h0;
            #pragma unroll
            for(int i=0;i<2;i++){
                int ch=tid+256*i;
                if(ch<384){
                    int r=ch/12, c=ch-r*12;
                    cpa16(st+S2_BHI+r*208+c*16, bh+(size_t)r*HDIM+c*8);
                }
            }
        }
        cpcommit();
    };

    const int mw=(w&3)*32, nw=(w>>2)*48;
    float C[2][6][4];
    #pragma unroll
    for(int i=0;i<2;i++)
        #pragma unroll
        for(int j=0;j<6;j++)
            #pragma unroll
            for(int q=0;q<4;q++) C[i][j][q]=0.f;

    const int rl=lane&15;
    const unsigned aswz=((rl>>1)&3);

    LOAD(0); LOAD(1); LOAD(2);
    for(int kc=0;kc<NCH;kc++){
        if(kc==NCH-1) cpwait<0>(); else cpwait<2>();
        __syncthreads();
        LOAD(kc+3);
        const unsigned ab=db+(unsigned)(kc&3)*S2_STAGE;
        #pragma unroll
        for(int ks=0;ks<2;ks++){
            unsigned a[2][4],b_h[6][2];
            const unsigned bbase=ab+S2_BHI+(unsigned)(ks*16+rl)*208;
            #pragma unroll
            for(int nt=0;nt<6;nt++)
                ldsm2t(b_h[nt],bbase+(nw+nt*8)*2);
            const unsigned aoff=ab+(unsigned)(mw+rl)*64+((((lane>>4)+ks*2)^aswz)*16);
            #pragma unroll
            for(int mt=0;mt<2;mt++) ldsm4(a[mt],aoff+mt*1024);
            #pragma unroll
            for(int mt=0;mt<2;mt++)
                #pragma unroll
                for(int nt=0;nt<6;nt++)
                    mma_fp(C[mt][nt],a[mt],b_h[nt]);
            #pragma unroll
            for(int mt=0;mt<2;mt++) ldsm4(a[mt],aoff+8192+mt*1024);
            #pragma unroll
            for(int mt=0;mt<2;mt++)
                #pragma unroll
                for(int nt=0;nt<6;nt++)
                    mma_fp(C[mt][nt],a[mt],b_h[nt]);
        }
    }

    // epilogue: + sum_e rw*bd, write fp32 out
    const int grp=lane>>2, tq=lane&3;
    #pragma unroll
    for(int nt=0;nt<6;nt++){
        const int col=h0+nw+nt*8+tq*2;
        #pragma unroll
        for(int mt=0;mt<2;mt++)
            #pragma unroll
            for(int h=0;h<2;h++){
                const int row=mw+mt*16+grp+h*8;
                float v0=C[mt][nt][2*h], v1=C[mt][nt][2*h+1];
                #pragma unroll
                for(int e2=0;e2<NEXP;e2++){
                    float r=sRw[row*8+e2];
                    v0=fmaf(r,bd[(size_t)e2*HDIM+col],v0);
                    v1=fmaf(r,bd[(size_t)e2*HDIM+col+1],v1);
                }
                float2 t; t.x=v0; t.y=v1;
                *(float2*)(out+(size_t)(m0+row)*HDIM+col)=t;
            }
    }
}

extern "C" void kernel_launch(void* const* d_in, const int* in_sizes, int n_in,
                              void* d_out, int out_size)
{
    const float* x  =(const float*)d_in[0];
    const float* rw =(const float*)d_in[1];
    const float* wgu=(const float*)d_in[2];
    const float* bgu=(const float*)d_in[3];
    const float* wd =(const float*)d_in[4];
    const float* bd =(const float*)d_in[5];
    float* out=(float*)d_out;

    cudaFuncSetAttribute(gemm1_kernel, cudaFuncAttributeMaxDynamicSharedMemorySize, 4*S1_STAGE);
    cudaFuncSetAttribute(gemm2_kernel, cudaFuncAttributeMaxDynamicSharedMemorySize, 4*S2_STAGE);

    split_kernel<<<592,256>>>((const float4*)x,  0, (long long)TOK*HDIM/4);
    split_kernel<<<592,256>>>((const float4*)wgu,1, (long long)NEXP*HDIM*GUCOLS/4);
    split_kernel<<<592,256>>>((const float4*)wd, 2, (long long)NEXP*DDIM*HDIM/4);
    gemm1_kernel<<<dim3(45,8,NEXP),256,4*S1_STAGE>>>(rw,bgu);
    gemm2_kernel<<<dim3(30,8),256,4*S2_STAGE>>>(rw,bd,out);
}

// round 8
// speedup vs baseline: 7.8678x; 1.7413x over previous
#include <cuda_runtime.h>
#include <cuda_fp16.h>
#include <math.h>

#define TOK 1024
#define HDIM 2880
#define DDIM 2880
#define NEXP 8
#define GUCOLS 5760
#define ALPHA 1.702f
#define LIMIT 7.0f

__device__ __align__(16) __half g_wgu_h[(size_t)NEXP*HDIM*GUCOLS];
__device__ __align__(16) __half g_wd_h [(size_t)NEXP*DDIM*HDIM];
__device__ __align__(16) __half g_x_h  [(size_t)TOK*HDIM];
__device__ __align__(16) __half g_a_h  [(size_t)NEXP*TOK*DDIM];

__device__ __forceinline__ unsigned su32(const void* p){
    unsigned a; asm("{ .reg .u64 t; cvta.to.shared.u64 t, %1; cvt.u32.u64 %0, t; }":"=r"(a):"l"(p)); return a;
}
template<int N> __device__ __forceinline__ void cpwait(){
    asm volatile("cp.async.wait_group %0;"::"n"(N):"memory");
}
__device__ __forceinline__ void cpcommit(){
    asm volatile("cp.async.commit_group;":::"memory");
}
__device__ __forceinline__ void cpa16(unsigned d, const void* s){
    asm volatile("cp.async.cg.shared.global [%0], [%1], 16;"::"r"(d),"l"(s):"memory");
}
__device__ __forceinline__ void ldsm4(unsigned* r, unsigned a){
    asm volatile("ldmatrix.sync.aligned.m8n8.x4.shared.b16 {%0,%1,%2,%3}, [%4];"
        :"=r"(r[0]),"=r"(r[1]),"=r"(r[2]),"=r"(r[3]):"r"(a));
}
__device__ __forceinline__ void ldsm2t(unsigned* r, unsigned a){
    asm volatile("ldmatrix.sync.aligned.m8n8.x2.trans.shared.b16 {%0,%1}, [%2];"
        :"=r"(r[0]),"=r"(r[1]):"r"(a));
}
__device__ __forceinline__ void mma_fp(float* c, const unsigned* a, const unsigned* b){
    asm volatile("mma.sync.aligned.m16n8k16.row.col.f32.f16.f16.f32 "
        "{%0,%1,%2,%3},{%4,%5,%6,%7},{%8,%9},{%0,%1,%2,%3};"
        : "+f"(c[0]),"+f"(c[1]),"+f"(c[2]),"+f"(c[3])
        : "r"(a[0]),"r"(a[1]),"r"(a[2]),"r"(a[3]),"r"(b[0]),"r"(b[1]));
}

// -------- fp32 -> fp16 convert --------
__global__ void cvt_kernel(const float4* __restrict__ src, int which, long long n4){
    __half* dst = (which==0)? g_x_h : (which==1)? g_wgu_h : g_wd_h;
    uint2* dp=(uint2*)dst;
    long long i=(long long)blockIdx.x*blockDim.x+threadIdx.x, st=(long long)gridDim.x*blockDim.x;
    for(; i<n4; i+=st){
        float4 f=src[i];
        uint2 v;
        v.x=(unsigned)__half_as_ushort(__float2half_rn(f.x))
           |((unsigned)__half_as_ushort(__float2half_rn(f.y))<<16);
        v.y=(unsigned)__half_as_ushort(__float2half_rn(f.z))
           |((unsigned)__half_as_ushort(__float2half_rn(f.w))<<16);
        dp[i]=v;
    }
}

// ======================= GEMM1: gate_up + SwiGLU =======================
// CTA tile: 128 tokens x 128 gu-cols. 256 thr, warps 2m x 4n (64x32).
// Stage 16KB (A 8K | B 8K), 4 stages, 2 CTAs/SM.
#define S1_STAGE 16384

__global__ __launch_bounds__(256,2)
void gemm1_kernel(const float* __restrict__ rw, const float* __restrict__ bgu)
{
    extern __shared__ __align__(16) char dsm[];
    __shared__ float sBias[128];
    __shared__ float sRw[128];
    const int tid=threadIdx.x, lane=tid&31, w=tid>>5;
    const int e=blockIdx.z, m0=blockIdx.y*128, c0=blockIdx.x*128, dbase=blockIdx.x*64;
    const unsigned db=su32(dsm);
    if(tid<128){
        sBias[tid]=bgu[(size_t)e*GUCOLS+c0+tid];
        sRw[tid]=rw[(size_t)(m0+tid)*NEXP+e];
    }

    const __half* xh = g_x_h + (size_t)m0*HDIM;
    const __half* wh = g_wgu_h + (size_t)e*HDIM*GUCOLS + c0;

    const int ar=tid>>2, ac=tid&3;
    const int br=tid>>4, bc=tid&15;
    const unsigned a_off = (unsigned)ar*64 + (unsigned)((ac ^ ((ar>>1)&3))*16);
    const unsigned b_off = (unsigned)br*256 + (unsigned)((bc ^ (br&7))*16);

    const int NCH=HDIM/32; // 90
    auto LOAD=[&](int kc){
        if(kc<NCH){
            const unsigned st=db+(unsigned)(kc&3)*S1_STAGE;
            const int k0=kc*32;
            cpa16(st+a_off,       xh+(size_t)ar*HDIM+k0+ac*8);
            cpa16(st+4096+a_off,  xh+(size_t)(ar+64)*HDIM+k0+ac*8);
            cpa16(st+8192+b_off,  wh+(size_t)(k0+br)*GUCOLS+bc*8);
            cpa16(st+12288+b_off, wh+(size_t)(k0+br+16)*GUCOLS+bc*8);
        }
        cpcommit();
    };

    const int mw=(w&1)*64, nw=(w>>1)*32;
    float C[4][4][4];
    #pragma unroll
    for(int i=0;i<4;i++)
        #pragma unroll
        for(int j=0;j<4;j++)
            #pragma unroll
            for(int q=0;q<4;q++) C[i][j][q]=0.f;

    const int rl=lane&15;
    const unsigned aswz=((rl>>1)&3);
    const unsigned bswz=(lane&7);

    LOAD(0); LOAD(1); LOAD(2);
    for(int kc=0;kc<NCH;kc++){
        if(kc==NCH-1) cpwait<0>(); else cpwait<2>();
        __syncthreads();
        LOAD(kc+3);
        const unsigned ab=db+(unsigned)(kc&3)*S1_STAGE;
        const unsigned bb=ab+8192;
        #pragma unroll
        for(int ks=0;ks<2;ks++){
            unsigned a[4][4],b_h[4][2];
            const unsigned boff=bb+(unsigned)(ks*16+rl)*256;
            #pragma unroll
            for(int nt=0;nt<4;nt++)
                ldsm2t(b_h[nt],boff+((((nw>>3)+nt)^bswz)*16));
            const unsigned aoff=ab+(unsigned)(mw+rl)*64+((((lane>>4)+ks*2)^aswz)*16);
            #pragma unroll
            for(int mt=0;mt<4;mt++) ldsm4(a[mt],aoff+mt*1024);
            #pragma unroll
            for(int mt=0;mt<4;mt++)
                #pragma unroll
                for(int nt=0;nt<4;nt++)
                    mma_fp(C[mt][nt],a[mt],b_h[nt]);
        }
    }
    __syncthreads();

    // epilogue: bias + SwiGLU + rw -> sv (fp32), then convert to act fp16
    float* sv=(float*)dsm;
    const int grp=lane>>2, tq=lane&3;
    #pragma unroll
    for(int mt=0;mt<4;mt++)
        #pragma unroll
        for(int nt=0;nt<4;nt++){
            const int colL=nw+nt*8+tq*2;
            const int d=(nw>>1)+nt*4+tq;
            #pragma unroll
            for(int h=0;h<2;h++){
                const int row=mw+mt*16+grp+h*8;
                float g=C[mt][nt][2*h]  +sBias[colL];
                float u=C[mt][nt][2*h+1]+sBias[colL+1];
                g=fminf(g,LIMIT);
                u=fminf(fmaxf(u,-LIMIT),LIMIT);
                float glu=g/(1.0f+__expf(-ALPHA*g));
                sv[row*68+d]=(u+1.0f)*glu*sRw[row];
            }
        }
    __syncthreads();
    {
        const int row=tid>>1, d0=(tid&1)*32;
        __half* oh=g_a_h+((size_t)e*TOK+m0+row)*DDIM+dbase+d0;
        #pragma unroll
        for(int j=0;j<32;j+=8){
            unsigned hv[4];
            #pragma unroll
            for(int q=0;q<4;q++){
                float aa=sv[row*68+d0+j+2*q], b=sv[row*68+d0+j+2*q+1];
                hv[q]=(unsigned)__half_as_ushort(__float2half_rn(aa))
                     |((unsigned)__half_as_ushort(__float2half_rn(b))<<16);
            }
            *(uint4*)(oh+j)=make_uint4(hv[0],hv[1],hv[2],hv[3]);
        }
    }
}

// ======================= GEMM2: down proj + bias + expert sum =======================
// CTA tile: 128 tokens x 96 h. 256 thr, warps 4m x 2n (32x48). K = 8*2880.
// Stage 14848 (A 8K | B 6656 pad208), 4 stages, 2 CTAs/SM.
#define S2_BHI 8192
#define S2_STAGE 14848

__global__ __launch_bounds__(256,2)
void gemm2_kernel(const float* __restrict__ rw, const float* __restrict__ bd,
                  float* __restrict__ out)
{
    extern __shared__ __align__(16) char dsm[];
    __shared__ float sRw[128*8];
    const int tid=threadIdx.x, lane=tid&31, w=tid>>5;
    const int m0=blockIdx.y*128, h0=blockIdx.x*96;
    const unsigned db=su32(dsm);
    for(int i=tid;i<1024;i+=256) sRw[i]=rw[(size_t)(m0+(i>>3))*NEXP+(i&7)];

    const int ar=tid>>2, ac=tid&3;
    const unsigned a_off = (unsigned)ar*64 + (unsigned)((ac ^ ((ar>>1)&3))*16);

    const int NCH=NEXP*90; // 720
    auto LOAD=[&](int kc){
        if(kc<NCH){
            const int e=kc/90, kl=(kc-e*90)*32;
            const unsigned st=db+(unsigned)(kc&3)*S2_STAGE;
            const __half* ah=g_a_h+((size_t)e*TOK+m0)*DDIM+kl;
            cpa16(st+a_off,       ah+(size_t)ar*DDIM+ac*8);
            cpa16(st+4096+a_off,  ah+(size_t)(ar+64)*DDIM+ac*8);
            const __half* bh=g_wd_h+((size_t)e*DDIM+kl)*HDIM+h0;
            #pragma unroll
            for(int i=0;i<2;i++){
                int ch=tid+256*i;
                if(ch<384){
                    int r=ch/12, c=ch-r*12;
                    cpa16(st+S2_BHI+r*208+c*16, bh+(size_t)r*HDIM+c*8);
                }
            }
        }
        cpcommit();
    };

    const int mw=(w&3)*32, nw=(w>>2)*48;
    float C[2][6][4];
    #pragma unroll
    for(int i=0;i<2;i++)
        #pragma unroll
        for(int j=0;j<6;j++)
            #pragma unroll
            for(int q=0;q<4;q++) C[i][j][q]=0.f;

    const int rl=lane&15;
    const unsigned aswz=((rl>>1)&3);

    LOAD(0); LOAD(1); LOAD(2);
    for(int kc=0;kc<NCH;kc++){
        if(kc==NCH-1) cpwait<0>(); else cpwait<2>();
        __syncthreads();
        LOAD(kc+3);
        const unsigned ab=db+(unsigned)(kc&3)*S2_STAGE;
        #pragma unroll
        for(int ks=0;ks<2;ks++){
            unsigned a[2][4],b_h[6][2];
            const unsigned bbase=ab+S2_BHI+(unsigned)(ks*16+rl)*208;
            #pragma unroll
            for(int nt=0;nt<6;nt++)
                ldsm2t(b_h[nt],bbase+(nw+nt*8)*2);
            const unsigned aoff=ab+(unsigned)(mw+rl)*64+((((lane>>4)+ks*2)^aswz)*16);
            #pragma unroll
            for(int mt=0;mt<2;mt++) ldsm4(a[mt],aoff+mt*1024);
            #pragma unroll
            for(int mt=0;mt<2;mt++)
                #pragma unroll
                for(int nt=0;nt<6;nt++)
                    mma_fp(C[mt][nt],a[mt],b_h[nt]);
        }
    }

    // epilogue: + sum_e rw*bd, write fp32 out
    const int grp=lane>>2, tq=lane&3;
    #pragma unroll
    for(int nt=0;nt<6;nt++){
        const int col=h0+nw+nt*8+tq*2;
        #pragma unroll
        for(int mt=0;mt<2;mt++)
            #pragma unroll
            for(int h=0;h<2;h++){
                const int row=mw+mt*16+grp+h*8;
                float v0=C[mt][nt][2*h], v1=C[mt][nt][2*h+1];
                #pragma unroll
                for(int e2=0;e2<NEXP;e2++){
                    float r=sRw[row*8+e2];
                    v0=fmaf(r,bd[(size_t)e2*HDIM+col],v0);
                    v1=fmaf(r,bd[(size_t)e2*HDIM+col+1],v1);
                }
                float2 t; t.x=v0; t.y=v1;
                *(float2*)(out+(size_t)(m0+row)*HDIM+col)=t;
            }
    }
}

extern "C" void kernel_launch(void* const* d_in, const int* in_sizes, int n_in,
                              void* d_out, int out_size)
{
    const float* x  =(const float*)d_in[0];
    const float* rw =(const float*)d_in[1];
    const float* wgu=(const float*)d_in[2];
    const float* bgu=(const float*)d_in[3];
    const float* wd =(const float*)d_in[4];
    const float* bd =(const float*)d_in[5];
    float* out=(float*)d_out;

    cudaFuncSetAttribute(gemm1_kernel, cudaFuncAttributeMaxDynamicSharedMemorySize, 4*S1_STAGE);
    cudaFuncSetAttribute(gemm2_kernel, cudaFuncAttributeMaxDynamicSharedMemorySize, 4*S2_STAGE);

    cvt_kernel<<<592,256>>>((const float4*)x,  0, (long long)TOK*HDIM/4);
    cvt_kernel<<<592,256>>>((const float4*)wgu,1, (long long)NEXP*HDIM*GUCOLS/4);
    cvt_kernel<<<592,256>>>((const float4*)wd, 2, (long long)NEXP*DDIM*HDIM/4);
    gemm1_kernel<<<dim3(45,8,NEXP),256,4*S1_STAGE>>>(rw,bgu);
    gemm2_kernel<<<dim3(30,8),256,4*S2_STAGE>>>(rw,bd,out);
}